// round 13
// baseline (speedup 1.0000x reference)
#include <cuda_runtime.h>
#include <cuda_fp16.h>
#include <math.h>
#include <stdint.h>

#define NN 4096
#define NE 16384
#define D 64
#define BG 16

// -------- device scratch (no allocations allowed) --------
__device__ float g_out[NN * D];
__device__ float g_h[NN * D];
__device__ float g_he[NE * D];
__device__ __half g_We[(size_t)NE * D * D];   // 134 MB: per-edge 64x64 weight fp16, [e][d*64+f]
__device__ float g_agg[NN * D];
__device__ float g_deg[NN];
__device__ float g_invdeg[NN];

__device__ __forceinline__ float lrelu(float x) { return x >= 0.f ? x : 0.01f * x; }
__device__ __forceinline__ float sigm(float x) { return 1.f / (1.f + expf(-x)); }
__device__ __forceinline__ uint32_t f2tf32(float x) {
    uint32_t u;
    asm("cvt.rna.tf32.f32 %0, %1;" : "=r"(u) : "f"(x));
    return u;
}

// -------- out = lrelu(x @ W0 + b0), h = out; also zero deg/agg --------
__global__ void __launch_bounds__(256) k_init(const float* __restrict__ x,
                                              const float* __restrict__ W0,
                                              const float* __restrict__ b0) {
    int id = blockIdx.x * 256 + threadIdx.x;     // 0 .. NN*D-1
    int n = id >> 6, f = id & 63;
    float acc = b0[f];
#pragma unroll
    for (int c = 0; c < 3; c++) acc += x[n * 3 + c] * W0[c * 64 + f];
    float v = lrelu(acc);
    g_out[id] = v;
    g_h[id] = v;
    if (f == 0) g_deg[n] = 0.f;
    g_agg[id] = 0.f;
}

// -------- he = lrelu(edge_attr @ We1 + be1) --------
__global__ void __launch_bounds__(256) k_he(const float* __restrict__ ea,
                                            const float* __restrict__ We1,
                                            const float* __restrict__ be1) {
    int id = blockIdx.x * 256 + threadIdx.x;     // 0 .. NE*D-1
    int e = id >> 6, f = id & 63;
    float acc = be1[f];
#pragma unroll
    for (int c = 0; c < 4; c++) acc += ea[e * 4 + c] * We1[c * 64 + f];
    g_he[id] = lrelu(acc);
}

// -------- deg / inv_deg --------
__global__ void __launch_bounds__(256) k_deg(const int* __restrict__ ei) {
    int e = blockIdx.x * 256 + threadIdx.x;
    if (e < NE) atomicAdd(&g_deg[ei[NE + e]], 1.f);
}
__global__ void __launch_bounds__(256) k_inv() {
    int i = blockIdx.x * 256 + threadIdx.x;
    if (i < NN) g_invdeg[i] = 1.f / fmaxf(g_deg[i], 1.f);
}

// -------- W_e = he @ We2 + be2   (M=16384, N=4096, K=64)  [tf32 tensor cores, fp16 out] --------
// 256 threads = 8 warps (4m x 2n), block tile 128x64, warp tile 32x32, full K in smem.
#define PA 68
#define PB 72
__global__ void __launch_bounds__(256) we_gemm_tc(const float* __restrict__ B,
                                                  const float* __restrict__ bias) {
    __shared__ uint32_t As[128 * PA];   // he tile, tf32 bits, pitch 68 (conflict-free)
    __shared__ uint32_t Bs[64 * PB];    // We2 tile, tf32 bits, pitch 72 (conflict-free)
    int tid = threadIdx.x;
    int n0 = blockIdx.x * 64;
    int m0 = blockIdx.y * 128;

#pragma unroll
    for (int c = 0; c < 8; c++) {
        int lin = c * 256 + tid;                 // 0..2047
        int m = lin >> 4, kq = lin & 15;
        float4 v = *(const float4*)&g_he[(m0 + m) * 64 + kq * 4];
        As[m * PA + kq * 4 + 0] = f2tf32(v.x);
        As[m * PA + kq * 4 + 1] = f2tf32(v.y);
        As[m * PA + kq * 4 + 2] = f2tf32(v.z);
        As[m * PA + kq * 4 + 3] = f2tf32(v.w);
    }
#pragma unroll
    for (int c = 0; c < 4; c++) {
        int lin = c * 256 + tid;                 // 0..1023
        int k = lin >> 4, nq = lin & 15;
        float4 v = *(const float4*)&B[k * 4096 + n0 + nq * 4];
        Bs[k * PB + nq * 4 + 0] = f2tf32(v.x);
        Bs[k * PB + nq * 4 + 1] = f2tf32(v.y);
        Bs[k * PB + nq * 4 + 2] = f2tf32(v.z);
        Bs[k * PB + nq * 4 + 3] = f2tf32(v.w);
    }
    __syncthreads();

    int warp = tid >> 5, lane = tid & 31;
    int wm = warp >> 1, wn = warp & 1;           // warp grid 4 x 2
    int gid = lane >> 2, tig = lane & 3;         // mma fragment coords

    float acc[2][4][4];
#pragma unroll
    for (int mi = 0; mi < 2; mi++)
#pragma unroll
        for (int ni = 0; ni < 4; ni++)
#pragma unroll
            for (int j = 0; j < 4; j++) acc[mi][ni][j] = 0.f;

#pragma unroll
    for (int k0 = 0; k0 < 64; k0 += 8) {
        uint32_t a[2][4];
#pragma unroll
        for (int mi = 0; mi < 2; mi++) {
            const uint32_t* ap = &As[(wm * 32 + mi * 16) * PA + k0];
            a[mi][0] = ap[gid * PA + tig];
            a[mi][1] = ap[(gid + 8) * PA + tig];
            a[mi][2] = ap[gid * PA + tig + 4];
            a[mi][3] = ap[(gid + 8) * PA + tig + 4];
        }
        uint32_t b[4][2];
#pragma unroll
        for (int ni = 0; ni < 4; ni++) {
            const uint32_t* bp = &Bs[k0 * PB + wn * 32 + ni * 8];
            b[ni][0] = bp[tig * PB + gid];
            b[ni][1] = bp[(tig + 4) * PB + gid];
        }
#pragma unroll
        for (int mi = 0; mi < 2; mi++)
#pragma unroll
            for (int ni = 0; ni < 4; ni++) {
                asm volatile(
                    "mma.sync.aligned.m16n8k8.row.col.f32.tf32.tf32.f32 "
                    "{%0,%1,%2,%3}, {%4,%5,%6,%7}, {%8,%9}, {%0,%1,%2,%3};"
                    : "+f"(acc[mi][ni][0]), "+f"(acc[mi][ni][1]),
                      "+f"(acc[mi][ni][2]), "+f"(acc[mi][ni][3])
                    : "r"(a[mi][0]), "r"(a[mi][1]), "r"(a[mi][2]), "r"(a[mi][3]),
                      "r"(b[ni][0]), "r"(b[ni][1]));
            }
    }

    // epilogue: add bias, convert to fp16, store
#pragma unroll
    for (int mi = 0; mi < 2; mi++) {
        int r0 = m0 + wm * 32 + mi * 16 + gid;
#pragma unroll
        for (int ni = 0; ni < 4; ni++) {
            int col = n0 + wn * 32 + ni * 8 + 2 * tig;
            float b0v = bias[col], b1v = bias[col + 1];
            __half2 v0 = __floats2half2_rn(acc[mi][ni][0] + b0v, acc[mi][ni][1] + b1v);
            __half2 v1 = __floats2half2_rn(acc[mi][ni][2] + b0v, acc[mi][ni][3] + b1v);
            *(__half2*)&g_We[(size_t)r0 * 4096 + col] = v0;
            *(__half2*)&g_We[(size_t)(r0 + 8) * 4096 + col] = v1;
        }
    }
}

// -------- msg[e] = out[src_e] @ W_e[e]; scatter-add into agg[dst_e] --------
// 32 edges/block, 8 threads/edge each owning 8 f's; fp16 W_e streamed as uint4 (128B/edge/d).
__global__ void __launch_bounds__(256) k_msg(const int* __restrict__ ei) {
    __shared__ float outs[32][65];     // pad: lanes read 4 distinct edges -> distinct banks
    __shared__ int dsts[32];
    int tid = threadIdx.x;
    int e0 = blockIdx.x * 32;
#pragma unroll
    for (int c = 0; c < 8; c++) {
        int lin = c * 256 + tid;                 // 0..2047
        int el = lin >> 6, d = lin & 63;
        int s = ei[e0 + el];
        outs[el][d] = g_out[s * 64 + d];
    }
    if (tid < 32) dsts[tid] = ei[NE + e0 + tid];
    __syncthreads();

    int el = tid >> 3, fo = tid & 7;             // 8 threads per edge
    const uint4* Wp = (const uint4*)&g_We[(size_t)(e0 + el) * 4096 + fo * 8];
    float acc[8];
#pragma unroll
    for (int j = 0; j < 8; j++) acc[j] = 0.f;

#pragma unroll 8
    for (int d = 0; d < 64; d++) {
        uint4 w = Wp[d * 8];                     // 8 halves = 16B
        float o = outs[el][d];
        __half2* hp = (__half2*)&w;
        float2 f0 = __half22float2(hp[0]);
        float2 f1 = __half22float2(hp[1]);
        float2 f2 = __half22float2(hp[2]);
        float2 f3 = __half22float2(hp[3]);
        acc[0] += o * f0.x;  acc[1] += o * f0.y;
        acc[2] += o * f1.x;  acc[3] += o * f1.y;
        acc[4] += o * f2.x;  acc[5] += o * f2.y;
        acc[6] += o * f3.x;  acc[7] += o * f3.y;
    }
    float* ap = &g_agg[dsts[el] * 64 + fo * 8];
#pragma unroll
    for (int j = 0; j < 8; j++) atomicAdd(ap + j, acc[j]);
}

// -------- fused node update: m = lrelu(agg*invdeg + out@root + conv_b); GRU step --------
// 32 nodes/block, weights staged in dynamic smem (transposed, pitch 193).
// Also zeroes g_agg for the next iteration (each element read exactly once here).
#define NODE_SMEM (47232 * 4)
__global__ void __launch_bounds__(256) k_node(const float* __restrict__ root,
                                              const float* __restrict__ conv_b,
                                              const float* __restrict__ Wih,
                                              const float* __restrict__ Whh,
                                              const float* __restrict__ bih,
                                              const float* __restrict__ bhh) {
    extern __shared__ float sm[];
    float* WihT = sm;                  // [64][193]
    float* WhhT = WihT + 64 * 193;     // [64][193]
    float* roots = WhhT + 64 * 193;    // [64*64]  [d*64+f]
    float* outs = roots + 4096;        // [32][64]
    float* hs = outs + 2048;           // [32][64]
    float* ms = hs + 2048;             // [32][64]
    float* gis = ms + 2048;            // [32][192]
    float* ghs = gis + 32 * 192;       // [32][192]

    int tid = threadIdx.x;
    int n0 = blockIdx.x * 32;

    for (int idx = tid; idx < 192 * 64; idx += 256) {
        int r = idx >> 6, d = idx & 63;
        WihT[d * 193 + r] = Wih[idx];
        WhhT[d * 193 + r] = Whh[idx];
    }
    for (int idx = tid; idx < 4096; idx += 256) roots[idx] = root[idx];
    for (int idx = tid; idx < 2048; idx += 256) {
        outs[idx] = g_out[n0 * 64 + idx];
        hs[idx] = g_h[n0 * 64 + idx];
    }
    __syncthreads();

    int f = tid & 63, g = tid >> 6;
    float cb = conv_b[f];
    for (int n = g; n < 32; n += 4) {
        int aidx = (n0 + n) * 64 + f;
        float acc = g_agg[aidx] * g_invdeg[n0 + n] + cb;
        g_agg[aidx] = 0.f;             // zero for next iteration's atomics
#pragma unroll
        for (int d4 = 0; d4 < 64; d4 += 4) {
            float4 o4 = *(float4*)&outs[n * 64 + d4];
            acc += o4.x * roots[d4 * 64 + f];
            acc += o4.y * roots[(d4 + 1) * 64 + f];
            acc += o4.z * roots[(d4 + 2) * 64 + f];
            acc += o4.w * roots[(d4 + 3) * 64 + f];
        }
        ms[n * 64 + f] = lrelu(acc);
    }
    __syncthreads();

    if (tid < 192) {
        int r = tid;
        float bi = bih[r], bh = bhh[r];
        for (int nb = 0; nb < 32; nb += 8) {
            float ai[8], ah[8];
#pragma unroll
            for (int j = 0; j < 8; j++) { ai[j] = bi; ah[j] = bh; }
#pragma unroll
            for (int d4 = 0; d4 < 64; d4 += 4) {
                float wi0 = WihT[(d4 + 0) * 193 + r], wh0 = WhhT[(d4 + 0) * 193 + r];
                float wi1 = WihT[(d4 + 1) * 193 + r], wh1 = WhhT[(d4 + 1) * 193 + r];
                float wi2 = WihT[(d4 + 2) * 193 + r], wh2 = WhhT[(d4 + 2) * 193 + r];
                float wi3 = WihT[(d4 + 3) * 193 + r], wh3 = WhhT[(d4 + 3) * 193 + r];
#pragma unroll
                for (int j = 0; j < 8; j++) {
                    float4 m4 = *(float4*)&ms[(nb + j) * 64 + d4];
                    float4 h4 = *(float4*)&hs[(nb + j) * 64 + d4];
                    ai[j] += m4.x * wi0 + m4.y * wi1 + m4.z * wi2 + m4.w * wi3;
                    ah[j] += h4.x * wh0 + h4.y * wh1 + h4.z * wh2 + h4.w * wh3;
                }
            }
#pragma unroll
            for (int j = 0; j < 8; j++) {
                gis[(nb + j) * 192 + r] = ai[j];
                ghs[(nb + j) * 192 + r] = ah[j];
            }
        }
    }
    __syncthreads();

    for (int n = g; n < 32; n += 4) {
        float ir = gis[n * 192 + f], hr = ghs[n * 192 + f];
        float iz = gis[n * 192 + 64 + f], hz = ghs[n * 192 + 64 + f];
        float in_ = gis[n * 192 + 128 + f], hn = ghs[n * 192 + 128 + f];
        float rr = sigm(ir + hr);
        float zz = sigm(iz + hz);
        float ng = tanhf(in_ + rr * hn);
        float hnew = (1.f - zz) * ng + zz * hs[n * 64 + f];
        int gidx = (n0 + n) * 64 + f;
        g_h[gidx] = hnew;
        g_out[gidx] = hnew;
    }
}

// -------- Set2Set (processing_steps=1, zero init => q from biases only) + output --------
__global__ void __launch_bounds__(1024, 1) k_final(const int* __restrict__ batch,
                                                   const float* __restrict__ lbih,
                                                   const float* __restrict__ lbhh,
                                                   const float* __restrict__ Wout,
                                                   const float* __restrict__ bout,
                                                   float* __restrict__ outp) {
    __shared__ float q_s[64];
    __shared__ float e_s[NN];
    __shared__ float red[1024];
    __shared__ int starts[BG + 1];
    __shared__ float emax[BG], asum[BG];
    __shared__ float rpool[BG * 64];
    int tid = threadIdx.x;

    if (tid < 64) {
        float gi = lbih[tid] + lbhh[tid];
        float gg = lbih[128 + tid] + lbhh[128 + tid];
        float go = lbih[192 + tid] + lbhh[192 + tid];
        float cl = sigm(gi) * tanhf(gg);   // c0 = 0, so forget-gate term drops
        q_s[tid] = sigm(go) * tanhf(cl);
    }
    if (tid <= BG) starts[tid] = NN;
    __syncthreads();

    // e[i] = <out[i], q>; find segment boundaries of sorted batch
    for (int i = tid; i < NN; i += 1024) {
        float acc = 0.f;
        const float4* op = (const float4*)&g_out[i * 64];
#pragma unroll
        for (int f4 = 0; f4 < 16; f4++) {
            float4 o = op[f4];
            float4 q = *(float4*)&q_s[f4 * 4];
            acc += o.x * q.x + o.y * q.y + o.z * q.z + o.w * q.w;
        }
        e_s[i] = acc;
        int b = batch[i];
        int bp = (i == 0) ? -1 : batch[i - 1];
        if (b != bp)
            for (int bb = bp + 1; bb <= b; bb++) starts[bb] = i;
    }
    __syncthreads();

    int grp = tid >> 6, lane = tid & 63;
    {
        float lm = -INFINITY;
        for (int i = starts[grp] + lane; i < starts[grp + 1]; i += 64) lm = fmaxf(lm, e_s[i]);
        red[tid] = lm;
    }
    __syncthreads();
    if (lane == 0) {
        float m = -INFINITY;
        for (int j = 0; j < 64; j++) m = fmaxf(m, red[grp * 64 + j]);
        emax[grp] = m;
    }
    __syncthreads();
    {
        float ls = 0.f;
        float em = emax[grp];
        for (int i = starts[grp] + lane; i < starts[grp + 1]; i += 64) {
            float a = expf(e_s[i] - em);
            e_s[i] = a;
            ls += a;
        }
        red[tid] = ls;
    }
    __syncthreads();
    if (lane == 0) {
        float s = 0.f;
        for (int j = 0; j < 64; j++) s += red[grp * 64 + j];
        asum[grp] = s;
    }
    __syncthreads();
    {
        int b = grp, f = lane;
        float acc = 0.f;
        int i1 = starts[b + 1];
        for (int i = starts[b]; i < i1; i++) acc += e_s[i] * g_out[i * 64 + f];
        float s = asum[b];
        rpool[b * 64 + f] = (s > 0.f) ? acc / s : 0.f;
    }
    __syncthreads();
    if (tid < 32) {
        int b = tid >> 1, o = tid & 1;
        float acc = bout[o];
#pragma unroll
        for (int j = 0; j < 64; j++) acc += q_s[j] * Wout[j * 2 + o];
#pragma unroll
        for (int j = 0; j < 64; j++) acc += rpool[b * 64 + j] * Wout[(64 + j) * 2 + o];
        outp[b * 2 + o] = acc;
    }
}

extern "C" void kernel_launch(void* const* d_in, const int* in_sizes, int n_in,
                              void* d_out, int out_size) {
    const float* x = (const float*)d_in[0];
    const float* edge_attr = (const float*)d_in[1];
    const int* edge_index = (const int*)d_in[2];
    const int* batch = (const int*)d_in[3];
    const float* W0 = (const float*)d_in[4];
    const float* b0 = (const float*)d_in[5];
    const float* We1 = (const float*)d_in[6];
    const float* be1 = (const float*)d_in[7];
    const float* We2 = (const float*)d_in[8];
    const float* be2 = (const float*)d_in[9];
    const float* root = (const float*)d_in[10];
    const float* conv_b = (const float*)d_in[11];
    const float* Wih = (const float*)d_in[12];
    const float* Whh = (const float*)d_in[13];
    const float* bih = (const float*)d_in[14];
    const float* bhh = (const float*)d_in[15];
    const float* lbih = (const float*)d_in[18];
    const float* lbhh = (const float*)d_in[19];
    const float* Wout = (const float*)d_in[20];
    const float* bout = (const float*)d_in[21];
    float* outp = (float*)d_out;

    cudaFuncSetAttribute(k_node, cudaFuncAttributeMaxDynamicSharedMemorySize, NODE_SMEM);

    k_init<<<(NN * D) / 256, 256>>>(x, W0, b0);
    k_he<<<(NE * D) / 256, 256>>>(edge_attr, We1, be1);
    k_deg<<<NE / 256, 256>>>(edge_index);
    k_inv<<<NN / 256, 256>>>();
    we_gemm_tc<<<dim3(64, 128), 256>>>(We2, be2);

    for (int it = 0; it < 6; it++) {
        k_msg<<<NE / 32, 256>>>(edge_index);
        k_node<<<NN / 32, 256, NODE_SMEM>>>(root, conv_b, Wih, Whh, bih, bhh);
    }
    k_final<<<1, 1024>>>(batch, lbih, lbhh, Wout, bout, outp);
}

// round 17
// speedup vs baseline: 1.0066x; 1.0066x over previous
#include <cuda_runtime.h>
#include <cuda_fp16.h>
#include <math.h>
#include <stdint.h>

#define NN 4096
#define NE 16384
#define D 64
#define BG 16

// -------- device scratch (no allocations allowed) --------
__device__ float g_out[NN * D];
__device__ float g_h[NN * D];
__device__ float g_he[NE * D];
__device__ __half g_We[(size_t)NE * D * D];   // 134 MB: per-edge 64x64 weight fp16, [e][d*64+f]
__device__ float g_agg[NN * D];
__device__ float g_deg[NN];
__device__ float g_invdeg[NN];

__device__ __forceinline__ float lrelu(float x) { return x >= 0.f ? x : 0.01f * x; }
__device__ __forceinline__ float sigm(float x) { return 1.f / (1.f + expf(-x)); }
__device__ __forceinline__ uint32_t f2tf32(float x) {
    uint32_t u;
    asm("cvt.rna.tf32.f32 %0, %1;" : "=r"(u) : "f"(x));
    return u;
}

// -------- out = lrelu(x @ W0 + b0), h = out; also zero deg/agg --------
__global__ void __launch_bounds__(256) k_init(const float* __restrict__ x,
                                              const float* __restrict__ W0,
                                              const float* __restrict__ b0) {
    int id = blockIdx.x * 256 + threadIdx.x;     // 0 .. NN*D-1
    int n = id >> 6, f = id & 63;
    float acc = b0[f];
#pragma unroll
    for (int c = 0; c < 3; c++) acc += x[n * 3 + c] * W0[c * 64 + f];
    float v = lrelu(acc);
    g_out[id] = v;
    g_h[id] = v;
    if (f == 0) g_deg[n] = 0.f;
    g_agg[id] = 0.f;
}

// -------- he = lrelu(edge_attr @ We1 + be1) --------
__global__ void __launch_bounds__(256) k_he(const float* __restrict__ ea,
                                            const float* __restrict__ We1,
                                            const float* __restrict__ be1) {
    int id = blockIdx.x * 256 + threadIdx.x;     // 0 .. NE*D-1
    int e = id >> 6, f = id & 63;
    float acc = be1[f];
#pragma unroll
    for (int c = 0; c < 4; c++) acc += ea[e * 4 + c] * We1[c * 64 + f];
    g_he[id] = lrelu(acc);
}

// -------- deg / inv_deg --------
__global__ void __launch_bounds__(256) k_deg(const int* __restrict__ ei) {
    int e = blockIdx.x * 256 + threadIdx.x;
    if (e < NE) atomicAdd(&g_deg[ei[NE + e]], 1.f);
}
__global__ void __launch_bounds__(256) k_inv() {
    int i = blockIdx.x * 256 + threadIdx.x;
    if (i < NN) g_invdeg[i] = 1.f / fmaxf(g_deg[i], 1.f);
}

// -------- W_e = he @ We2 + be2   (M=16384, N=4096, K=64)  [tf32 tensor cores, fp16 out] --------
// 256 threads = 8 warps (4m x 2n), block tile 128x64, warp tile 32x32, full K in smem.
#define PA 68
#define PB 72
__global__ void __launch_bounds__(256) we_gemm_tc(const float* __restrict__ B,
                                                  const float* __restrict__ bias) {
    __shared__ uint32_t As[128 * PA];   // he tile, tf32 bits, pitch 68 (conflict-free)
    __shared__ uint32_t Bs[64 * PB];    // We2 tile, tf32 bits, pitch 72 (conflict-free)
    int tid = threadIdx.x;
    int n0 = blockIdx.x * 64;
    int m0 = blockIdx.y * 128;

#pragma unroll
    for (int c = 0; c < 8; c++) {
        int lin = c * 256 + tid;                 // 0..2047
        int m = lin >> 4, kq = lin & 15;
        float4 v = *(const float4*)&g_he[(m0 + m) * 64 + kq * 4];
        As[m * PA + kq * 4 + 0] = f2tf32(v.x);
        As[m * PA + kq * 4 + 1] = f2tf32(v.y);
        As[m * PA + kq * 4 + 2] = f2tf32(v.z);
        As[m * PA + kq * 4 + 3] = f2tf32(v.w);
    }
#pragma unroll
    for (int c = 0; c < 4; c++) {
        int lin = c * 256 + tid;                 // 0..1023
        int k = lin >> 4, nq = lin & 15;
        float4 v = *(const float4*)&B[k * 4096 + n0 + nq * 4];
        Bs[k * PB + nq * 4 + 0] = f2tf32(v.x);
        Bs[k * PB + nq * 4 + 1] = f2tf32(v.y);
        Bs[k * PB + nq * 4 + 2] = f2tf32(v.z);
        Bs[k * PB + nq * 4 + 3] = f2tf32(v.w);
    }
    __syncthreads();

    int warp = tid >> 5, lane = tid & 31;
    int wm = warp >> 1, wn = warp & 1;           // warp grid 4 x 2
    int gid = lane >> 2, tig = lane & 3;         // mma fragment coords

    float acc[2][4][4];
#pragma unroll
    for (int mi = 0; mi < 2; mi++)
#pragma unroll
        for (int ni = 0; ni < 4; ni++)
#pragma unroll
            for (int j = 0; j < 4; j++) acc[mi][ni][j] = 0.f;

#pragma unroll
    for (int k0 = 0; k0 < 64; k0 += 8) {
        uint32_t a[2][4];
#pragma unroll
        for (int mi = 0; mi < 2; mi++) {
            const uint32_t* ap = &As[(wm * 32 + mi * 16) * PA + k0];
            a[mi][0] = ap[gid * PA + tig];
            a[mi][1] = ap[(gid + 8) * PA + tig];
            a[mi][2] = ap[gid * PA + tig + 4];
            a[mi][3] = ap[(gid + 8) * PA + tig + 4];
        }
        uint32_t b[4][2];
#pragma unroll
        for (int ni = 0; ni < 4; ni++) {
            const uint32_t* bp = &Bs[k0 * PB + wn * 32 + ni * 8];
            b[ni][0] = bp[tig * PB + gid];
            b[ni][1] = bp[(tig + 4) * PB + gid];
        }
#pragma unroll
        for (int mi = 0; mi < 2; mi++)
#pragma unroll
            for (int ni = 0; ni < 4; ni++) {
                asm volatile(
                    "mma.sync.aligned.m16n8k8.row.col.f32.tf32.tf32.f32 "
                    "{%0,%1,%2,%3}, {%4,%5,%6,%7}, {%8,%9}, {%0,%1,%2,%3};"
                    : "+f"(acc[mi][ni][0]), "+f"(acc[mi][ni][1]),
                      "+f"(acc[mi][ni][2]), "+f"(acc[mi][ni][3])
                    : "r"(a[mi][0]), "r"(a[mi][1]), "r"(a[mi][2]), "r"(a[mi][3]),
                      "r"(b[ni][0]), "r"(b[ni][1]));
            }
    }

    // epilogue: add bias, convert to fp16, store
#pragma unroll
    for (int mi = 0; mi < 2; mi++) {
        int r0 = m0 + wm * 32 + mi * 16 + gid;
#pragma unroll
        for (int ni = 0; ni < 4; ni++) {
            int col = n0 + wn * 32 + ni * 8 + 2 * tig;
            float b0v = bias[col], b1v = bias[col + 1];
            __half2 v0 = __floats2half2_rn(acc[mi][ni][0] + b0v, acc[mi][ni][1] + b1v);
            __half2 v1 = __floats2half2_rn(acc[mi][ni][2] + b0v, acc[mi][ni][3] + b1v);
            *(__half2*)&g_We[(size_t)r0 * 4096 + col] = v0;
            *(__half2*)&g_We[(size_t)(r0 + 8) * 4096 + col] = v1;
        }
    }
}

// -------- msg[e] = out[src_e] @ W_e[e]; scatter-add into agg[dst_e] --------
// 32 edges/block, 8 threads/edge each owning 8 f's; fp16 W_e streamed as uint4 (128B/edge/d).
__global__ void __launch_bounds__(256) k_msg(const int* __restrict__ ei) {
    __shared__ float outs[32][65];     // pad: lanes read 4 distinct edges -> distinct banks
    __shared__ int dsts[32];
    int tid = threadIdx.x;
    int e0 = blockIdx.x * 32;
#pragma unroll
    for (int c = 0; c < 8; c++) {
        int lin = c * 256 + tid;                 // 0..2047
        int el = lin >> 6, d = lin & 63;
        int s = ei[e0 + el];
        outs[el][d] = g_out[s * 64 + d];
    }
    if (tid < 32) dsts[tid] = ei[NE + e0 + tid];
    __syncthreads();

    int el = tid >> 3, fo = tid & 7;             // 8 threads per edge
    const uint4* Wp = (const uint4*)&g_We[(size_t)(e0 + el) * 4096 + fo * 8];
    float acc[8];
#pragma unroll
    for (int j = 0; j < 8; j++) acc[j] = 0.f;

#pragma unroll 8
    for (int d = 0; d < 64; d++) {
        uint4 w = Wp[d * 8];                     // 8 halves = 16B
        float o = outs[el][d];
        __half2* hp = (__half2*)&w;
        float2 f0 = __half22float2(hp[0]);
        float2 f1 = __half22float2(hp[1]);
        float2 f2 = __half22float2(hp[2]);
        float2 f3 = __half22float2(hp[3]);
        acc[0] += o * f0.x;  acc[1] += o * f0.y;
        acc[2] += o * f1.x;  acc[3] += o * f1.y;
        acc[4] += o * f2.x;  acc[5] += o * f2.y;
        acc[6] += o * f3.x;  acc[7] += o * f3.y;
    }
    float* ap = &g_agg[dsts[el] * 64 + fo * 8];
#pragma unroll
    for (int j = 0; j < 8; j++) atomicAdd(ap + j, acc[j]);
}

// -------- fused node update: m = lrelu(agg*invdeg + out@root + conv_b); GRU step --------
// 32 nodes/block, weights staged in dynamic smem (transposed, pitch 193).
// Also zeroes g_agg for the next iteration (each element read exactly once here).
#define NODE_SMEM (47232 * 4)
__global__ void __launch_bounds__(256) k_node(const float* __restrict__ root,
                                              const float* __restrict__ conv_b,
                                              const float* __restrict__ Wih,
                                              const float* __restrict__ Whh,
                                              const float* __restrict__ bih,
                                              const float* __restrict__ bhh) {
    extern __shared__ float sm[];
    float* WihT = sm;                  // [64][193]
    float* WhhT = WihT + 64 * 193;     // [64][193]
    float* roots = WhhT + 64 * 193;    // [64*64]  [d*64+f]
    float* outs = roots + 4096;        // [32][64]
    float* hs = outs + 2048;           // [32][64]
    float* ms = hs + 2048;             // [32][64]
    float* gis = ms + 2048;            // [32][192]
    float* ghs = gis + 32 * 192;       // [32][192]

    int tid = threadIdx.x;
    int n0 = blockIdx.x * 32;

    for (int idx = tid; idx < 192 * 64; idx += 256) {
        int r = idx >> 6, d = idx & 63;
        WihT[d * 193 + r] = Wih[idx];
        WhhT[d * 193 + r] = Whh[idx];
    }
    for (int idx = tid; idx < 4096; idx += 256) roots[idx] = root[idx];
    for (int idx = tid; idx < 2048; idx += 256) {
        outs[idx] = g_out[n0 * 64 + idx];
        hs[idx] = g_h[n0 * 64 + idx];
    }
    __syncthreads();

    int f = tid & 63, g = tid >> 6;
    float cb = conv_b[f];
    for (int n = g; n < 32; n += 4) {
        int aidx = (n0 + n) * 64 + f;
        float acc = g_agg[aidx] * g_invdeg[n0 + n] + cb;
        g_agg[aidx] = 0.f;             // zero for next iteration's atomics
#pragma unroll
        for (int d4 = 0; d4 < 64; d4 += 4) {
            float4 o4 = *(float4*)&outs[n * 64 + d4];
            acc += o4.x * roots[d4 * 64 + f];
            acc += o4.y * roots[(d4 + 1) * 64 + f];
            acc += o4.z * roots[(d4 + 2) * 64 + f];
            acc += o4.w * roots[(d4 + 3) * 64 + f];
        }
        ms[n * 64 + f] = lrelu(acc);
    }
    __syncthreads();

    if (tid < 192) {
        int r = tid;
        float bi = bih[r], bh = bhh[r];
        for (int nb = 0; nb < 32; nb += 8) {
            float ai[8], ah[8];
#pragma unroll
            for (int j = 0; j < 8; j++) { ai[j] = bi; ah[j] = bh; }
#pragma unroll
            for (int d4 = 0; d4 < 64; d4 += 4) {
                float wi0 = WihT[(d4 + 0) * 193 + r], wh0 = WhhT[(d4 + 0) * 193 + r];
                float wi1 = WihT[(d4 + 1) * 193 + r], wh1 = WhhT[(d4 + 1) * 193 + r];
                float wi2 = WihT[(d4 + 2) * 193 + r], wh2 = WhhT[(d4 + 2) * 193 + r];
                float wi3 = WihT[(d4 + 3) * 193 + r], wh3 = WhhT[(d4 + 3) * 193 + r];
#pragma unroll
                for (int j = 0; j < 8; j++) {
                    float4 m4 = *(float4*)&ms[(nb + j) * 64 + d4];
                    float4 h4 = *(float4*)&hs[(nb + j) * 64 + d4];
                    ai[j] += m4.x * wi0 + m4.y * wi1 + m4.z * wi2 + m4.w * wi3;
                    ah[j] += h4.x * wh0 + h4.y * wh1 + h4.z * wh2 + h4.w * wh3;
                }
            }
#pragma unroll
            for (int j = 0; j < 8; j++) {
                gis[(nb + j) * 192 + r] = ai[j];
                ghs[(nb + j) * 192 + r] = ah[j];
            }
        }
    }
    __syncthreads();

    for (int n = g; n < 32; n += 4) {
        float ir = gis[n * 192 + f], hr = ghs[n * 192 + f];
        float iz = gis[n * 192 + 64 + f], hz = ghs[n * 192 + 64 + f];
        float in_ = gis[n * 192 + 128 + f], hn = ghs[n * 192 + 128 + f];
        float rr = sigm(ir + hr);
        float zz = sigm(iz + hz);
        float ng = tanhf(in_ + rr * hn);
        float hnew = (1.f - zz) * ng + zz * hs[n * 64 + f];
        int gidx = (n0 + n) * 64 + f;
        g_h[gidx] = hnew;
        g_out[gidx] = hnew;
    }
}

// -------- Set2Set (processing_steps=1, zero init => q from biases only) + output --------
__global__ void __launch_bounds__(1024, 1) k_final(const int* __restrict__ batch,
                                                   const float* __restrict__ lbih,
                                                   const float* __restrict__ lbhh,
                                                   const float* __restrict__ Wout,
                                                   const float* __restrict__ bout,
                                                   float* __restrict__ outp) {
    __shared__ float q_s[64];
    __shared__ float e_s[NN];
    __shared__ float red[1024];
    __shared__ int starts[BG + 1];
    __shared__ float emax[BG], asum[BG];
    __shared__ float rpool[BG * 64];
    int tid = threadIdx.x;

    if (tid < 64) {
        float gi = lbih[tid] + lbhh[tid];
        float gg = lbih[128 + tid] + lbhh[128 + tid];
        float go = lbih[192 + tid] + lbhh[192 + tid];
        float cl = sigm(gi) * tanhf(gg);   // c0 = 0, so forget-gate term drops
        q_s[tid] = sigm(go) * tanhf(cl);
    }
    if (tid <= BG) starts[tid] = NN;
    __syncthreads();

    // e[i] = <out[i], q>; find segment boundaries of sorted batch
    for (int i = tid; i < NN; i += 1024) {
        float acc = 0.f;
        const float4* op = (const float4*)&g_out[i * 64];
#pragma unroll
        for (int f4 = 0; f4 < 16; f4++) {
            float4 o = op[f4];
            float4 q = *(float4*)&q_s[f4 * 4];
            acc += o.x * q.x + o.y * q.y + o.z * q.z + o.w * q.w;
        }
        e_s[i] = acc;
        int b = batch[i];
        int bp = (i == 0) ? -1 : batch[i - 1];
        if (b != bp)
            for (int bb = bp + 1; bb <= b; bb++) starts[bb] = i;
    }
    __syncthreads();

    int grp = tid >> 6, lane = tid & 63;
    {
        float lm = -INFINITY;
        for (int i = starts[grp] + lane; i < starts[grp + 1]; i += 64) lm = fmaxf(lm, e_s[i]);
        red[tid] = lm;
    }
    __syncthreads();
    if (lane == 0) {
        float m = -INFINITY;
        for (int j = 0; j < 64; j++) m = fmaxf(m, red[grp * 64 + j]);
        emax[grp] = m;
    }
    __syncthreads();
    {
        float ls = 0.f;
        float em = emax[grp];
        for (int i = starts[grp] + lane; i < starts[grp + 1]; i += 64) {
            float a = expf(e_s[i] - em);
            e_s[i] = a;
            ls += a;
        }
        red[tid] = ls;
    }
    __syncthreads();
    if (lane == 0) {
        float s = 0.f;
        for (int j = 0; j < 64; j++) s += red[grp * 64 + j];
        asum[grp] = s;
    }
    __syncthreads();
    {
        int b = grp, f = lane;
        float acc = 0.f;
        int i1 = starts[b + 1];
        for (int i = starts[b]; i < i1; i++) acc += e_s[i] * g_out[i * 64 + f];
        float s = asum[b];
        rpool[b * 64 + f] = (s > 0.f) ? acc / s : 0.f;
    }
    __syncthreads();
    if (tid < 32) {
        int b = tid >> 1, o = tid & 1;
        float acc = bout[o];
#pragma unroll
        for (int j = 0; j < 64; j++) acc += q_s[j] * Wout[j * 2 + o];
#pragma unroll
        for (int j = 0; j < 64; j++) acc += rpool[b * 64 + j] * Wout[(64 + j) * 2 + o];
        outp[b * 2 + o] = acc;
    }
}

extern "C" void kernel_launch(void* const* d_in, const int* in_sizes, int n_in,
                              void* d_out, int out_size) {
    const float* x = (const float*)d_in[0];
    const float* edge_attr = (const float*)d_in[1];
    const int* edge_index = (const int*)d_in[2];
    const int* batch = (const int*)d_in[3];
    const float* W0 = (const float*)d_in[4];
    const float* b0 = (const float*)d_in[5];
    const float* We1 = (const float*)d_in[6];
    const float* be1 = (const float*)d_in[7];
    const float* We2 = (const float*)d_in[8];
    const float* be2 = (const float*)d_in[9];
    const float* root = (const float*)d_in[10];
    const float* conv_b = (const float*)d_in[11];
    const float* Wih = (const float*)d_in[12];
    const float* Whh = (const float*)d_in[13];
    const float* bih = (const float*)d_in[14];
    const float* bhh = (const float*)d_in[15];
    const float* lbih = (const float*)d_in[18];
    const float* lbhh = (const float*)d_in[19];
    const float* Wout = (const float*)d_in[20];
    const float* bout = (const float*)d_in[21];
    float* outp = (float*)d_out;

    cudaFuncSetAttribute(k_node, cudaFuncAttributeMaxDynamicSharedMemorySize, NODE_SMEM);

    k_init<<<(NN * D) / 256, 256>>>(x, W0, b0);
    k_he<<<(NE * D) / 256, 256>>>(edge_attr, We1, be1);
    k_deg<<<NE / 256, 256>>>(edge_index);
    k_inv<<<NN / 256, 256>>>();
    we_gemm_tc<<<dim3(64, 128), 256>>>(We2, be2);

    for (int it = 0; it < 6; it++) {
        k_msg<<<NE / 32, 256>>>(edge_index);
        k_node<<<NN / 32, 256, NODE_SMEM>>>(root, conv_b, Wih, Whh, bih, bhh);
    }
    k_final<<<1, 1024>>>(batch, lbih, lbhh, Wout, bout, outp);
}